// round 9
// baseline (speedup 1.0000x reference)
#include <cuda_runtime.h>
#include <cuda_bf16.h>
#include <cstdint>

#define Bdim 4
#define Tdim 4
#define Cdim 32
#define Ndim 16384
#define Fdim 64
#define Kdim 9
#define CK   288
#define NCH  6
#define CHK  48             // logical k per chunk, 3 k16-steps
#define TILE_N 128

// smem layout (bytes)
#define PA 112              // A row: 48 bf16 = 96B + 16 pad
#define PB 272              // B row: 128 bf16 = 256B + 16 pad
#define ASZ (64 * PA)       // 7168 per A buffer
#define BSZ (CHK * PB)      // 13056 per B buffer
#define OFF_XS 0            // float [32][136] = 17408
#define OFF_WS 17408        // float [9][128]  =  4608
#define OFF_A  22016        // 4 bufs (parity x hi/lo) * 7168  = 28672
#define OFF_B  50688        // 4 bufs (parity x hi/lo) * 13056 = 52224
#define SMEM_TOTAL 102912

// named barriers: FULL[p] = 1+p (producer arrives, consumer waits)
//                 FREE[p] = 3+p (consumer arrives, producer waits)
#define BAR_SYNC(id)   asm volatile("bar.sync %0, 256;"   :: "r"(id) : "memory")
#define BAR_ARRIVE(id) asm volatile("bar.arrive %0, 256;" :: "r"(id) : "memory")

// Pre-split A: [h][t][f][ck] bf16 (h=0 hi, h=1 lo)
__device__ __align__(16) __nv_bfloat16 g_wA[2][Tdim * Fdim * CK];

__global__ void prep_w(const float* __restrict__ w) {
    int idx = blockIdx.x * 256 + threadIdx.x;
    if (idx >= Tdim * Fdim * CK) return;
    int ck = idx % CK;
    int fm = idx / CK;
    int f  = fm & 63;
    int t  = fm >> 6;
    int c  = ck / 9, kk = ck - 9 * c;
    float val = w[((t * Fdim + f) * Cdim + c) * Kdim + kk];
    __nv_bfloat16 hi = __float2bfloat16_rn(val);
    g_wA[0][idx] = hi;
    g_wA[1][idx] = __float2bfloat16_rn(val - __bfloat162float(hi));
}

__device__ __forceinline__ uint32_t smem_u32(const void* p) {
    uint32_t a;
    asm("{ .reg .u64 t; cvta.to.shared.u64 t, %1; cvt.u32.u64 %0, t; }" : "=r"(a) : "l"(p));
    return a;
}

#define LDSM_X4(r0,r1,r2,r3, addr) \
    asm volatile("ldmatrix.sync.aligned.m8n8.x4.shared.b16 {%0,%1,%2,%3}, [%4];" \
        : "=r"(r0),"=r"(r1),"=r"(r2),"=r"(r3) : "r"(addr))

#define LDSM_X4T(r0,r1,r2,r3, addr) \
    asm volatile("ldmatrix.sync.aligned.m8n8.x4.trans.shared.b16 {%0,%1,%2,%3}, [%4];" \
        : "=r"(r0),"=r"(r1),"=r"(r2),"=r"(r3) : "r"(addr))

#define MMA16816(c, a0,a1,a2,a3, b0,b1) \
    asm volatile("mma.sync.aligned.m16n8k16.row.col.f32.bf16.bf16.f32 " \
        "{%0,%1,%2,%3},{%4,%5,%6,%7},{%8,%9},{%0,%1,%2,%3};" \
        : "+f"((c)[0]),"+f"((c)[1]),"+f"((c)[2]),"+f"((c)[3]) \
        : "r"(a0),"r"(a1),"r"(a2),"r"(a3),"r"(b0),"r"(b1))

#define CP_ASYNC16(dst, src) \
    asm volatile("cp.async.ca.shared.global [%0], [%1], 16;" :: "r"(dst), "l"(src))

__global__ __launch_bounds__(256, 2)
void sepconv_mma_kernel(const float* __restrict__ x,
                        const float* __restrict__ coords,
                        const unsigned* __restrict__ sigma_p,
                        float* __restrict__ out)
{
    extern __shared__ __align__(16) unsigned char sm[];
    float* xs = (float*)(sm + OFF_XS);     // [32][136], halo
    float* ws = (float*)(sm + OFF_WS);     // [9][128]

    const int tid  = threadIdx.x;
    const int warp = tid >> 5;
    const int lane = tid & 31;
    const int bt   = blockIdx.y;
    const int t    = bt & (Tdim - 1);
    const int n0   = blockIdx.x * TILE_N;

    unsigned sb = *sigma_p;
    float sigma = (sb < 0x01000000u) ? (float)(int)sb : __uint_as_float(sb);
    float inv_sigma = 1.0f / sigma;

    // ---- stage x tile (halo, zero-padded) — all 256 threads ----
    const float* xb = x + (size_t)bt * Cdim * Ndim;
    for (int idx = tid; idx < Cdim * 136; idx += 256) {
        int c = idx / 136, i = idx - c * 136;
        int m = n0 + i - 4;
        xs[idx] = (m >= 0 && m < Ndim) ? xb[c * Ndim + m] : 0.0f;
    }
    // ---- distance weights ws[k][n] ----
    const float* cb = coords + (size_t)bt * 3 * Ndim;
    for (int idx = tid; idx < Kdim * TILE_N; idx += 256) {
        int k = idx >> 7, n = idx & 127;
        int mc = n0 + n, mt2 = mc + k - 4;
        float cx = 0.f, cy = 0.f, cz = 0.f;
        if (mt2 >= 0 && mt2 < Ndim) { cx = cb[mt2]; cy = cb[Ndim + mt2]; cz = cb[2 * Ndim + mt2]; }
        float dx = cx - cb[mc], dy = cy - cb[Ndim + mc], dz = cz - cb[2 * Ndim + mc];
        float d2 = dx * dx + dy * dy + dz * dz;
        ws[k * 128 + n] = fmaxf(1.0f - sqrtf(d2) * inv_sigma, 0.0f);
    }
    __syncthreads();

    const uint32_t smb = smem_u32(sm);

    if (warp >= 4) {
        // ================= PRODUCER warps (4): build A+B chunks =================
        const int ptid = tid - 128;            // 0..127
        const int n2   = ptid & 63;            // n pair
        const int ckr  = ptid >> 6;            // 0..1

        for (int ch = 0; ch < NCH; ch++) {
            const int p = ch & 1;
            if (ch >= 2) BAR_SYNC(3 + p);      // wait buffer free

            // A chunk via cp.async: 2 bufs x 64 rows x 6 uint4 = 768
            {
                const uint4* src0 = (const uint4*)g_wA[0] + ((size_t)t * Fdim) * 36 + ch * 6;
                const uint4* src1 = (const uint4*)g_wA[1] + ((size_t)t * Fdim) * 36 + ch * 6;
                #pragma unroll
                for (int it = 0; it < 6; it++) {
                    int idx = it * 128 + ptid;     // 0..767
                    int h   = idx / 384;
                    int rem = idx - h * 384;
                    int row = rem / 6, col = rem - row * 6;
                    uint32_t dst = smb + OFF_A +
                        (uint32_t)((p * 2 + h) * ASZ + row * PA + col * 16);
                    const uint4* src = (h ? src1 : src0) + (size_t)row * 36 + col;
                    CP_ASYNC16(dst, src);
                }
                asm volatile("cp.async.commit_group;" ::: "memory");
            }
            // B build: hi (truncation) and lo (exact residual, rn)
            {
                unsigned* bh32 = (unsigned*)(sm + OFF_B + (p * 2) * BSZ);
                unsigned* bl32 = (unsigned*)(sm + OFF_B + (p * 2 + 1) * BSZ);
                #pragma unroll
                for (int cc = 0; cc < CHK; cc += 2) {
                    int ccl = cc + ckr;
                    int ck = ch * CHK + ccl;
                    int c = ck / 9, k = ck - 9 * c;
                    int nn = 2 * n2;
                    float v0 = xs[c * 136 + nn + k]     * ws[k * 128 + nn];
                    float v1 = xs[c * 136 + nn + 1 + k] * ws[k * 128 + nn + 1];
                    unsigned u0 = __float_as_uint(v0), u1 = __float_as_uint(v1);
                    unsigned hh;
                    asm("prmt.b32 %0, %1, %2, 0x7632;" : "=r"(hh) : "r"(u0), "r"(u1));
                    float r0 = v0 - __uint_as_float(u0 & 0xFFFF0000u);
                    float r1 = v1 - __uint_as_float(u1 & 0xFFFF0000u);
                    __nv_bfloat162 l2 = __floats2bfloat162_rn(r0, r1);
                    bh32[ccl * (PB / 4) + n2] = hh;
                    bl32[ccl * (PB / 4) + n2] = *(unsigned*)&l2;
                }
            }
            asm volatile("cp.async.wait_group 0;" ::: "memory");
            BAR_ARRIVE(1 + p);                 // publish full
        }
    } else {
        // ================= CONSUMER warps (4): MMA, 16f x 128n each ============
        const int mt = warp;                   // m-tile (16 f rows)
        float acc[16][4];
        #pragma unroll
        for (int j = 0; j < 16; j++)
            #pragma unroll
            for (int q = 0; q < 4; q++) acc[j][q] = 0.0f;

        const int g = lane >> 3, rr = lane & 7;
        const uint32_t a_off = (uint32_t)((mt * 16 + (g & 1) * 8 + rr) * PA + (g >> 1) * 16);
        const uint32_t b_off = (uint32_t)(((g & 1) * 8 + rr) * PB + ((g >> 1) * 8) * 2);

        for (int ch = 0; ch < NCH; ch++) {
            const int p = ch & 1;
            BAR_SYNC(1 + p);                   // wait buffer full

            const uint32_t ah_base = smb + OFF_A + (p * 2) * ASZ + a_off;
            const uint32_t al_base = ah_base + ASZ;
            const uint32_t bh_base = smb + OFF_B + (p * 2) * BSZ + b_off;
            const uint32_t bl_base = bh_base + BSZ;

            #pragma unroll
            for (int ks = 0; ks < 3; ks++) {
                uint32_t ah[4], al[4];
                LDSM_X4(ah[0], ah[1], ah[2], ah[3], ah_base + ks * 32);
                LDSM_X4(al[0], al[1], al[2], al[3], al_base + ks * 32);
                #pragma unroll
                for (int half = 0; half < 2; half++) {
                    const uint32_t hofs = ks * 16 * PB + half * 128;
                    uint32_t bh[4][4];
                    #pragma unroll
                    for (int bp = 0; bp < 4; bp++)
                        LDSM_X4T(bh[bp][0], bh[bp][1], bh[bp][2], bh[bp][3],
                                 bh_base + hofs + bp * 32);
                    #pragma unroll
                    for (int bp = 0; bp < 4; bp++) {
                        MMA16816(acc[half*8 + bp*2],     ah[0],ah[1],ah[2],ah[3],
                                 bh[bp][0], bh[bp][1]);
                        MMA16816(acc[half*8 + bp*2 + 1], ah[0],ah[1],ah[2],ah[3],
                                 bh[bp][2], bh[bp][3]);
                    }
                    #pragma unroll
                    for (int bp = 0; bp < 4; bp++) {
                        uint32_t bl[4];
                        LDSM_X4T(bl[0], bl[1], bl[2], bl[3], bl_base + hofs + bp * 32);
                        MMA16816(acc[half*8 + bp*2],     ah[0],ah[1],ah[2],ah[3],
                                 bl[0], bl[1]);
                        MMA16816(acc[half*8 + bp*2 + 1], ah[0],ah[1],ah[2],ah[3],
                                 bl[2], bl[3]);
                        MMA16816(acc[half*8 + bp*2],     al[0],al[1],al[2],al[3],
                                 bh[bp][0], bh[bp][1]);
                        MMA16816(acc[half*8 + bp*2 + 1], al[0],al[1],al[2],al[3],
                                 bh[bp][2], bh[bp][3]);
                    }
                }
            }
            BAR_ARRIVE(3 + p);                 // release buffer
        }

        // ---- epilogue: register fragments -> gmem ----
        float* ob = out + (size_t)bt * Fdim * Ndim;
        const int drow = lane >> 2;
        const int dcol = (lane & 3) * 2;
        #pragma unroll
        for (int j = 0; j < 16; j++) {
            int f  = mt * 16 + drow;
            int nc = n0 + j * 8 + dcol;
            *(float2*)&ob[(size_t)f * Ndim + nc]       = make_float2(acc[j][0], acc[j][1]);
            *(float2*)&ob[(size_t)(f + 8) * Ndim + nc] = make_float2(acc[j][2], acc[j][3]);
        }
    }
}

extern "C" void kernel_launch(void* const* d_in, const int* in_sizes, int n_in,
                              void* d_out, int out_size)
{
    const float*    x      = (const float*)d_in[0];
    const float*    coords = (const float*)d_in[1];
    const float*    w      = (const float*)d_in[2];
    const unsigned* sigma  = (const unsigned*)d_in[3];
    float*          out    = (float*)d_out;

    static int smem_set = 0;
    if (!smem_set) {
        cudaFuncSetAttribute(sepconv_mma_kernel,
                             cudaFuncAttributeMaxDynamicSharedMemorySize, SMEM_TOTAL);
        smem_set = 1;
    }

    prep_w<<<(Tdim * Fdim * CK + 255) / 256, 256>>>(w);

    dim3 grid(Ndim / TILE_N, Bdim * Tdim);
    sepconv_mma_kernel<<<grid, 256, SMEM_TOTAL>>>(x, coords, sigma, out);
}

// round 10
// speedup vs baseline: 1.7952x; 1.7952x over previous
#include <cuda_runtime.h>
#include <cuda_bf16.h>
#include <cstdint>

#define Bdim 4
#define Tdim 4
#define Cdim 32
#define Ndim 16384
#define Fdim 64
#define Kdim 9
#define TILE_N 128

// pitches (bytes): row = [hi 32 bf16 | lo 32 bf16 | 16B pad] = 144 (stride%32w==4, conflict-free)
#define PROW 144
// smem layout
#define OFF_A   0                       // 9 k-chunks x 64 f-rows x 144B = 82944
#define OFF_XT  82944                   // 136 n-rows x 144B = 19584
#define OFF_WS  102528                  // float [9][128] = 4608
#define SMEM_TOTAL 107136

// Pre-split weights, smem image layout: [t][k][f][ hi 32c | lo 32c | pad16 ]
__device__ __align__(16) unsigned char g_wA9[Tdim * Kdim * Fdim * PROW];   // 324 KB

__global__ void prep_w(const float* __restrict__ w) {
    int idx = blockIdx.x * 256 + threadIdx.x;
    int nElem = Tdim * Kdim * Fdim * Cdim;          // 73728
    if (idx < nElem) {
        int c = idx & 31;
        int f = (idx >> 5) & 63;
        int r = idx >> 11;                           // t*9 + k
        int k = r % 9, t = r / 9;
        float val = w[((t * Fdim + f) * Cdim + c) * Kdim + k];
        __nv_bfloat16 hi = __float2bfloat16_rn(val);
        __nv_bfloat16 lo = __float2bfloat16_rn(val - __bfloat162float(hi));
        size_t base = ((size_t)r * Fdim + f) * PROW;
        *(unsigned short*)(g_wA9 + base + 2 * c)      = __bfloat16_as_ushort(hi);
        *(unsigned short*)(g_wA9 + base + 64 + 2 * c) = __bfloat16_as_ushort(lo);
    } else {
        int rrow = idx - nElem;                      // pad rows
        if (rrow < Tdim * Kdim * Fdim) {
            uint4 z = make_uint4(0, 0, 0, 0);
            *(uint4*)(g_wA9 + (size_t)rrow * PROW + 128) = z;
        }
    }
}

__device__ __forceinline__ uint32_t smem_u32(const void* p) {
    uint32_t a;
    asm("{ .reg .u64 t; cvta.to.shared.u64 t, %1; cvt.u32.u64 %0, t; }" : "=r"(a) : "l"(p));
    return a;
}

#define LDSM_X4(r0,r1,r2,r3, addr) \
    asm volatile("ldmatrix.sync.aligned.m8n8.x4.shared.b16 {%0,%1,%2,%3}, [%4];" \
        : "=r"(r0),"=r"(r1),"=r"(r2),"=r"(r3) : "r"(addr))

#define MMA16816(c, a, b0,b1) \
    asm volatile("mma.sync.aligned.m16n8k16.row.col.f32.bf16.bf16.f32 " \
        "{%0,%1,%2,%3},{%4,%5,%6,%7},{%8,%9},{%0,%1,%2,%3};" \
        : "+f"((c)[0]),"+f"((c)[1]),"+f"((c)[2]),"+f"((c)[3]) \
        : "r"((a)[0]),"r"((a)[1]),"r"((a)[2]),"r"((a)[3]),"r"(b0),"r"(b1))

#define CP_ASYNC16(dst, src) \
    asm volatile("cp.async.ca.shared.global [%0], [%1], 16;" :: "r"(dst), "l"(src))

__global__ __launch_bounds__(256, 2)
void sepconv_mma_kernel(const float* __restrict__ x,
                        const float* __restrict__ coords,
                        const unsigned* __restrict__ sigma_p,
                        float* __restrict__ out)
{
    extern __shared__ __align__(16) unsigned char sm[];
    float* ws = (float*)(sm + OFF_WS);     // [9][128]

    const int tid  = threadIdx.x;
    const int warp = tid >> 5;
    const int lane = tid & 31;
    const int bt   = blockIdx.y;
    const int t    = bt & (Tdim - 1);
    const int n0   = blockIdx.x * TILE_N;
    const uint32_t smb = smem_u32(sm);

    unsigned sb = *sigma_p;
    float sigma = (sb < 0x01000000u) ? (float)(int)sb : __uint_as_float(sb);
    float inv_sigma = 1.0f / sigma;

    // ---- A: all 9 k-chunks via cp.async (82944 B = 5184 uint4) ----
    {
        const uint4* asrc = (const uint4*)(g_wA9 + (size_t)t * (Kdim * Fdim * PROW));
        for (int i = tid; i < 5184; i += 256)
            CP_ASYNC16(smb + OFF_A + i * 16, asrc + i);
        asm volatile("cp.async.commit_group;" ::: "memory");
    }

    // ---- xT build: x[c][n0+i-4] -> hi/lo bf16 at xT[i][c], 136 rows ----
    const float* xb = x + (size_t)bt * Cdim * Ndim;
    #pragma unroll
    for (int it = 0; it < 9; it++) {
        int idx = it * 256 + tid;
        if (idx < 16 * 136) {
            int cp2 = idx / 136;                 // c pair 0..15
            int i   = idx - cp2 * 136;
            int m   = n0 + i - 4;
            int c0  = cp2 * 2;
            float v0 = 0.0f, v1 = 0.0f;
            if (m >= 0 && m < Ndim) {
                v0 = xb[(size_t)c0 * Ndim + m];
                v1 = xb[(size_t)(c0 + 1) * Ndim + m];
            }
            unsigned u0 = __float_as_uint(v0), u1 = __float_as_uint(v1);
            unsigned hh;
            asm("prmt.b32 %0, %1, %2, 0x7632;" : "=r"(hh) : "r"(u0), "r"(u1));
            float r0 = v0 - __uint_as_float(u0 & 0xFFFF0000u);   // exact
            float r1 = v1 - __uint_as_float(u1 & 0xFFFF0000u);   // exact
            __nv_bfloat162 l2 = __floats2bfloat162_rn(r0, r1);
            *(unsigned*)(sm + OFF_XT + i * PROW + 2 * c0)      = hh;
            *(unsigned*)(sm + OFF_XT + i * PROW + 64 + 2 * c0) = *(unsigned*)&l2;
        }
    }

    // ---- distance weights ws[k][n] (fp32, applied post-MMA) ----
    const float* cb = coords + (size_t)bt * 3 * Ndim;
    for (int idx = tid; idx < Kdim * TILE_N; idx += 256) {
        int k = idx >> 7, n = idx & 127;
        int mc = n0 + n, mt2 = mc + k - 4;
        float cx = 0.f, cy = 0.f, cz = 0.f;
        if (mt2 >= 0 && mt2 < Ndim) { cx = cb[mt2]; cy = cb[Ndim + mt2]; cz = cb[2 * Ndim + mt2]; }
        float dx = cx - cb[mc], dy = cy - cb[Ndim + mc], dz = cz - cb[2 * Ndim + mc];
        float d2 = dx * dx + dy * dy + dz * dz;
        ws[k * 128 + n] = fmaxf(1.0f - sqrtf(d2) * inv_sigma, 0.0f);
    }
    asm volatile("cp.async.wait_group 0;" ::: "memory");
    __syncthreads();                             // the ONLY barrier

    // ---- 9 GEMMs (K=32 each), per-k scaled accumulation ----
    const int mt = warp & 3;                     // 16 f rows
    const int nh = warp >> 2;                    // 64 n cols
    const int g  = lane >> 3, rr = lane & 7;

    // A frag lane offset (non-trans, rows=f): row mt*16+(g&1)*8+rr, colhalf (g>>1)*16
    const uint32_t aoff = (uint32_t)((mt * 16 + (g & 1) * 8 + rr) * PROW + (g >> 1) * 16);
    // B frag lane offset (non-trans, rows=n): khalf=(lane>>3)&1 -> colhalf, nhalf=lane>>4
    const uint32_t boff = (uint32_t)(((lane >> 4) * 8 + (lane & 7) + nh * 64) * PROW
                                     + ((lane >> 3) & 1) * 16);

    float acc[8][4];
    #pragma unroll
    for (int j = 0; j < 8; j++)
        #pragma unroll
        for (int q = 0; q < 4; q++) acc[j][q] = 0.0f;

    const int wcol0 = nh * 64 + (lane & 3) * 2;

    #pragma unroll
    for (int k = 0; k < 9; k++) {
        const uint32_t ab = smb + OFF_A + (uint32_t)k * (Fdim * PROW) + aoff;
        uint32_t ah[2][4], al[2][4];
        LDSM_X4(ah[0][0], ah[0][1], ah[0][2], ah[0][3], ab);            // s=0 hi
        LDSM_X4(ah[1][0], ah[1][1], ah[1][2], ah[1][3], ab + 32);       // s=1 hi
        LDSM_X4(al[0][0], al[0][1], al[0][2], al[0][3], ab + 64);       // s=0 lo
        LDSM_X4(al[1][0], al[1][1], al[1][2], al[1][3], ab + 96);       // s=1 lo

        const uint32_t bk = smb + OFF_XT + (uint32_t)k * PROW + boff;

        #pragma unroll
        for (int h2 = 0; h2 < 2; h2++) {
            float tmp[4][4];
            #pragma unroll
            for (int j = 0; j < 4; j++)
                #pragma unroll
                for (int q = 0; q < 4; q++) tmp[j][q] = 0.0f;

            #pragma unroll
            for (int s = 0; s < 2; s++) {
                #pragma unroll
                for (int g16 = 0; g16 < 2; g16++) {
                    const uint32_t ba = bk + (uint32_t)((h2 * 32 + g16 * 16) * PROW + s * 32);
                    uint32_t bh[4], bl[4];
                    LDSM_X4(bh[0], bh[1], bh[2], bh[3], ba);
                    LDSM_X4(bl[0], bl[1], bl[2], bl[3], ba + 64);
                    const int j = g16 * 2;
                    MMA16816(tmp[j],     ah[s], bh[0], bh[1]);
                    MMA16816(tmp[j + 1], ah[s], bh[2], bh[3]);
                    MMA16816(tmp[j],     ah[s], bl[0], bl[1]);
                    MMA16816(tmp[j + 1], ah[s], bl[2], bl[3]);
                    MMA16816(tmp[j],     al[s], bh[0], bh[1]);
                    MMA16816(tmp[j + 1], al[s], bh[2], bh[3]);
                }
            }
            // scale by w[k][n] and accumulate (w exact fp32)
            #pragma unroll
            for (int j = 0; j < 4; j++) {
                float2 wv = *(float2*)(ws + k * 128 + (h2 * 32 + j * 8 + wcol0));
                acc[h2 * 4 + j][0] += wv.x * tmp[j][0];
                acc[h2 * 4 + j][1] += wv.y * tmp[j][1];
                acc[h2 * 4 + j][2] += wv.x * tmp[j][2];
                acc[h2 * 4 + j][3] += wv.y * tmp[j][3];
            }
        }
    }

    // ---- epilogue: register fragments -> gmem ----
    float* ob = out + (size_t)bt * Fdim * Ndim;
    const int drow = lane >> 2;
    const int dcol = (lane & 3) * 2;
    #pragma unroll
    for (int j = 0; j < 8; j++) {
        int f  = mt * 16 + drow;
        int nc = n0 + nh * 64 + j * 8 + dcol;
        *(float2*)&ob[(size_t)f * Ndim + nc]       = make_float2(acc[j][0], acc[j][1]);
        *(float2*)&ob[(size_t)(f + 8) * Ndim + nc] = make_float2(acc[j][2], acc[j][3]);
    }
}

extern "C" void kernel_launch(void* const* d_in, const int* in_sizes, int n_in,
                              void* d_out, int out_size)
{
    const float*    x      = (const float*)d_in[0];
    const float*    coords = (const float*)d_in[1];
    const float*    w      = (const float*)d_in[2];
    const unsigned* sigma  = (const unsigned*)d_in[3];
    float*          out    = (float*)d_out;

    static int smem_set = 0;
    if (!smem_set) {
        cudaFuncSetAttribute(sepconv_mma_kernel,
                             cudaFuncAttributeMaxDynamicSharedMemorySize, SMEM_TOTAL);
        smem_set = 1;
    }

    int prepN = Tdim * Kdim * Fdim * Cdim + Tdim * Kdim * Fdim;
    prep_w<<<(prepN + 255) / 256, 256>>>(w);

    dim3 grid(Ndim / TILE_N, Bdim * Tdim);
    sepconv_mma_kernel<<<grid, 256, SMEM_TOTAL>>>(x, coords, sigma, out);
}

// round 12
// speedup vs baseline: 2.7373x; 1.5248x over previous
#include <cuda_runtime.h>
#include <cuda_fp16.h>
#include <cstdint>

#define Bdim 4
#define Tdim 4
#define Cdim 32
#define Ndim 16384
#define Fdim 64
#define Kdim 9
#define TILE_N 128

// pitch: 32 fp16 = 64B data + 16B pad = 80B (20-word stride, conflict-free ldmatrix)
#define PROW 80
// smem layout
#define OFF_A   0                       // 9 k x 64 f x 80B = 46080
#define OFF_XT  46080                   // 136 n-rows x 80B = 10880
#define OFF_WS  56960                   // float [9][128]   =  4608
#define SMEM_TOTAL 61568

// Pre-converted fp16 weights, smem image layout: [t][k][f][32 c fp16 | pad16]
__device__ __align__(16) unsigned char g_wA9[Tdim * Kdim * Fdim * PROW];   // 180 KB

__global__ void prep_w(const float* __restrict__ w) {
    int idx = blockIdx.x * 256 + threadIdx.x;
    if (idx >= Tdim * Kdim * Fdim * Cdim) return;     // 73728
    int c = idx & 31;
    int f = (idx >> 5) & 63;
    int r = idx >> 11;                                // t*9 + k
    int k = r % 9, t = r / 9;
    float val = w[((t * Fdim + f) * Cdim + c) * Kdim + k];
    size_t base = ((size_t)r * Fdim + f) * PROW;
    *(unsigned short*)(g_wA9 + base + 2 * c) = __half_as_ushort(__float2half_rn(val));
}

__device__ __forceinline__ uint32_t smem_u32(const void* p) {
    uint32_t a;
    asm("{ .reg .u64 t; cvta.to.shared.u64 t, %1; cvt.u32.u64 %0, t; }" : "=r"(a) : "l"(p));
    return a;
}

#define LDSM_X4(r0,r1,r2,r3, addr) \
    asm volatile("ldmatrix.sync.aligned.m8n8.x4.shared.b16 {%0,%1,%2,%3}, [%4];" \
        : "=r"(r0),"=r"(r1),"=r"(r2),"=r"(r3) : "r"(addr))

#define MMAF16(c, a, b0,b1) \
    asm volatile("mma.sync.aligned.m16n8k16.row.col.f32.f16.f16.f32 " \
        "{%0,%1,%2,%3},{%4,%5,%6,%7},{%8,%9},{%0,%1,%2,%3};" \
        : "+f"((c)[0]),"+f"((c)[1]),"+f"((c)[2]),"+f"((c)[3]) \
        : "r"((a)[0]),"r"((a)[1]),"r"((a)[2]),"r"((a)[3]),"r"(b0),"r"(b1))

#define CP_ASYNC16(dst, src) \
    asm volatile("cp.async.ca.shared.global [%0], [%1], 16;" :: "r"(dst), "l"(src))

__global__ __launch_bounds__(256, 3)
void sepconv_mma_kernel(const float* __restrict__ x,
                        const float* __restrict__ coords,
                        const unsigned* __restrict__ sigma_p,
                        float* __restrict__ out)
{
    extern __shared__ __align__(16) unsigned char sm[];
    float* ws = (float*)(sm + OFF_WS);     // [9][128]

    const int tid  = threadIdx.x;
    const int warp = tid >> 5;
    const int lane = tid & 31;
    const int bt   = blockIdx.y;
    const int t    = bt & (Tdim - 1);
    const int n0   = blockIdx.x * TILE_N;
    const uint32_t smb = smem_u32(sm);

    unsigned sb = *sigma_p;
    float sigma = (sb < 0x01000000u) ? (float)(int)sb : __uint_as_float(sb);
    float inv_sigma = 1.0f / sigma;

    // ---- A: all 9 k-chunks via cp.async (46080 B = 2880 uint4) ----
    {
        const uint4* asrc = (const uint4*)(g_wA9 + (size_t)t * (Kdim * Fdim * PROW));
        for (int i = tid; i < 2880; i += 256)
            CP_ASYNC16(smb + OFF_A + i * 16, asrc + i);
        asm volatile("cp.async.commit_group;" ::: "memory");
    }

    // ---- xT build: x[c][n0+i-4] -> fp16 at xT[i][c], 136 rows ----
    const float* xb = x + (size_t)bt * Cdim * Ndim;
    #pragma unroll
    for (int it = 0; it < 9; it++) {
        int idx = it * 256 + tid;
        if (idx < 16 * 136) {
            int cp2 = idx / 136;                 // c pair 0..15
            int i   = idx - cp2 * 136;
            int m   = n0 + i - 4;
            int c0  = cp2 * 2;
            float v0 = 0.0f, v1 = 0.0f;
            if (m >= 0 && m < Ndim) {
                v0 = xb[(size_t)c0 * Ndim + m];
                v1 = xb[(size_t)(c0 + 1) * Ndim + m];
            }
            __half2 h2v = __floats2half2_rn(v0, v1);
            *(unsigned*)(sm + OFF_XT + i * PROW + 4 * cp2) = *(unsigned*)&h2v;
        }
    }

    // ---- distance weights ws[k][n] (fp32, applied post-MMA) ----
    const float* cb = coords + (size_t)bt * 3 * Ndim;
    for (int idx = tid; idx < Kdim * TILE_N; idx += 256) {
        int k = idx >> 7, n = idx & 127;
        int mc = n0 + n, mt2 = mc + k - 4;
        float cx = 0.f, cy = 0.f, cz = 0.f;
        if (mt2 >= 0 && mt2 < Ndim) { cx = cb[mt2]; cy = cb[Ndim + mt2]; cz = cb[2 * Ndim + mt2]; }
        float dx = cx - cb[mc], dy = cy - cb[Ndim + mc], dz = cz - cb[2 * Ndim + mc];
        float d2 = dx * dx + dy * dy + dz * dz;
        ws[k * 128 + n] = fmaxf(1.0f - sqrtf(d2) * inv_sigma, 0.0f);
    }
    asm volatile("cp.async.wait_group 0;" ::: "memory");
    __syncthreads();                             // the ONLY barrier

    // ---- 9 GEMMs (K=32 each), per-k scaled accumulation ----
    const int mt = warp & 3;                     // 16 f rows
    const int nh = warp >> 2;                    // 64 n cols
    const int g  = lane >> 3, rr = lane & 7;

    const uint32_t aoff = (uint32_t)((mt * 16 + (g & 1) * 8 + rr) * PROW + (g >> 1) * 16);
    const uint32_t boff = (uint32_t)(((lane >> 4) * 8 + (lane & 7) + nh * 64) * PROW
                                     + ((lane >> 3) & 1) * 16);

    float acc[8][4];
    #pragma unroll
    for (int j = 0; j < 8; j++)
        #pragma unroll
        for (int q = 0; q < 4; q++) acc[j][q] = 0.0f;

    const int wcol0 = nh * 64 + (lane & 3) * 2;

    #pragma unroll
    for (int k = 0; k < 9; k++) {
        const uint32_t ab = smb + OFF_A + (uint32_t)k * (Fdim * PROW) + aoff;
        uint32_t ah[2][4];
        LDSM_X4(ah[0][0], ah[0][1], ah[0][2], ah[0][3], ab);        // k16 half 0
        LDSM_X4(ah[1][0], ah[1][1], ah[1][2], ah[1][3], ab + 32);   // k16 half 1

        const uint32_t bk = smb + OFF_XT + (uint32_t)k * PROW + boff;

        #pragma unroll
        for (int h2 = 0; h2 < 2; h2++) {
            float tmp[4][4];
            #pragma unroll
            for (int j = 0; j < 4; j++)
                #pragma unroll
                for (int q = 0; q < 4; q++) tmp[j][q] = 0.0f;

            #pragma unroll
            for (int s = 0; s < 2; s++) {
                #pragma unroll
                for (int g16 = 0; g16 < 2; g16++) {
                    const uint32_t ba = bk + (uint32_t)((h2 * 32 + g16 * 16) * PROW + s * 32);
                    uint32_t bh[4];
                    LDSM_X4(bh[0], bh[1], bh[2], bh[3], ba);
                    const int j = g16 * 2;
                    MMAF16(tmp[j],     ah[s], bh[0], bh[1]);
                    MMAF16(tmp[j + 1], ah[s], bh[2], bh[3]);
                }
            }
            // scale by w[k][n] and accumulate (w exact fp32)
            #pragma unroll
            for (int j = 0; j < 4; j++) {
                float2 wv = *(float2*)(ws + k * 128 + (h2 * 32 + j * 8 + wcol0));
                acc[h2 * 4 + j][0] += wv.x * tmp[j][0];
                acc[h2 * 4 + j][1] += wv.y * tmp[j][1];
                acc[h2 * 4 + j][2] += wv.x * tmp[j][2];
                acc[h2 * 4 + j][3] += wv.y * tmp[j][3];
            }
        }
    }

    // ---- epilogue: register fragments -> gmem ----
    float* ob = out + (size_t)bt * Fdim * Ndim;
    const int drow = lane >> 2;
    const int dcol = (lane & 3) * 2;
    #pragma unroll
    for (int j = 0; j < 8; j++) {
        int f  = mt * 16 + drow;
        int nc = n0 + nh * 64 + j * 8 + dcol;
        *(float2*)&ob[(size_t)f * Ndim + nc]       = make_float2(acc[j][0], acc[j][1]);
        *(float2*)&ob[(size_t)(f + 8) * Ndim + nc] = make_float2(acc[j][2], acc[j][3]);
    }
}

extern "C" void kernel_launch(void* const* d_in, const int* in_sizes, int n_in,
                              void* d_out, int out_size)
{
    const float*    x      = (const float*)d_in[0];
    const float*    coords = (const float*)d_in[1];
    const float*    w      = (const float*)d_in[2];
    const unsigned* sigma  = (const unsigned*)d_in[3];
    float*          out    = (float*)d_out;

    static int smem_set = 0;
    if (!smem_set) {
        cudaFuncSetAttribute(sepconv_mma_kernel,
                             cudaFuncAttributeMaxDynamicSharedMemorySize, SMEM_TOTAL);
        smem_set = 1;
    }

    prep_w<<<(Tdim * Kdim * Fdim * Cdim + 255) / 256, 256>>>(w);

    dim3 grid(Ndim / TILE_N, Bdim * Tdim);
    sepconv_mma_kernel<<<grid, 256, SMEM_TOTAL>>>(x, coords, sigma, out);
}

// round 13
// speedup vs baseline: 3.1777x; 1.1609x over previous
#include <cuda_runtime.h>
#include <cuda_fp16.h>
#include <cstdint>

#define Bdim 4
#define Tdim 4
#define Cdim 32
#define Ndim 16384
#define Fdim 64
#define Kdim 9
#define TILE_N 128
#define THREADS 128

// pitch: 32 fp16 = 64B data + 16B pad = 80B (20-word stride, conflict-free ldmatrix)
#define PROW 80
// smem layout
#define OFF_A   0                       // 9 k x 64 f x 80B = 46080
#define OFF_XT  46080                   // 136 n-rows x 80B = 10880
#define OFF_WS  56960                   // float [9][128]   =  4608
#define SMEM_TOTAL 61568

// Pre-converted fp16 weights, smem image layout: [t][k][f][32 c fp16 | pad16]
__device__ __align__(16) unsigned char g_wA9[Tdim * Kdim * Fdim * PROW];   // 180 KB

__global__ void prep_w(const float* __restrict__ w) {
    int idx = blockIdx.x * 256 + threadIdx.x;
    if (idx >= Tdim * Kdim * Fdim * Cdim) return;     // 73728
    int c = idx & 31;
    int f = (idx >> 5) & 63;
    int r = idx >> 11;                                // t*9 + k
    int k = r % 9, t = r / 9;
    float val = w[((t * Fdim + f) * Cdim + c) * Kdim + k];
    size_t base = ((size_t)r * Fdim + f) * PROW;
    *(unsigned short*)(g_wA9 + base + 2 * c) = __half_as_ushort(__float2half_rn(val));
}

__device__ __forceinline__ uint32_t smem_u32(const void* p) {
    uint32_t a;
    asm("{ .reg .u64 t; cvta.to.shared.u64 t, %1; cvt.u32.u64 %0, t; }" : "=r"(a) : "l"(p));
    return a;
}

#define LDSM_X4(r0,r1,r2,r3, addr) \
    asm volatile("ldmatrix.sync.aligned.m8n8.x4.shared.b16 {%0,%1,%2,%3}, [%4];" \
        : "=r"(r0),"=r"(r1),"=r"(r2),"=r"(r3) : "r"(addr))

#define MMAF16(c, a, b0,b1) \
    asm volatile("mma.sync.aligned.m16n8k16.row.col.f32.f16.f16.f32 " \
        "{%0,%1,%2,%3},{%4,%5,%6,%7},{%8,%9},{%0,%1,%2,%3};" \
        : "+f"((c)[0]),"+f"((c)[1]),"+f"((c)[2]),"+f"((c)[3]) \
        : "r"((a)[0]),"r"((a)[1]),"r"((a)[2]),"r"((a)[3]),"r"(b0),"r"(b1))

#define CP_ASYNC16(dst, src) \
    asm volatile("cp.async.ca.shared.global [%0], [%1], 16;" :: "r"(dst), "l"(src))

__global__ __launch_bounds__(THREADS, 3)
void sepconv_mma_kernel(const float* __restrict__ x,
                        const float* __restrict__ coords,
                        const unsigned* __restrict__ sigma_p,
                        float* __restrict__ out)
{
    extern __shared__ __align__(16) unsigned char sm[];
    float* ws = (float*)(sm + OFF_WS);     // [9][128]

    const int tid  = threadIdx.x;
    const int warp = tid >> 5;             // 0..3
    const int lane = tid & 31;
    const int bt   = blockIdx.y;
    const int t    = bt & (Tdim - 1);
    const int n0   = blockIdx.x * TILE_N;
    const uint32_t smb = smem_u32(sm);

    unsigned sb = *sigma_p;
    float sigma = (sb < 0x01000000u) ? (float)(int)sb : __uint_as_float(sb);
    float inv_sigma = 1.0f / sigma;

    // ---- A: all 9 k-chunks via cp.async (46080 B = 2880 uint4) ----
    {
        const uint4* asrc = (const uint4*)(g_wA9 + (size_t)t * (Kdim * Fdim * PROW));
        for (int i = tid; i < 2880; i += THREADS)
            CP_ASYNC16(smb + OFF_A + i * 16, asrc + i);
        asm volatile("cp.async.commit_group;" ::: "memory");
    }

    // ---- xT build: x[c][n0+i-4] -> fp16 at xT[i][c], 136 rows ----
    const float* xb = x + (size_t)bt * Cdim * Ndim;
    #pragma unroll
    for (int it = 0; it < 17; it++) {
        int idx = it * THREADS + tid;
        if (idx < 16 * 136) {
            int cp2 = idx / 136;                 // c pair 0..15
            int i   = idx - cp2 * 136;
            int m   = n0 + i - 4;
            float v0 = 0.0f, v1 = 0.0f;
            if (m >= 0 && m < Ndim) {
                v0 = xb[(size_t)(cp2 * 2) * Ndim + m];
                v1 = xb[(size_t)(cp2 * 2 + 1) * Ndim + m];
            }
            __half2 h2v = __floats2half2_rn(v0, v1);
            *(unsigned*)(sm + OFF_XT + i * PROW + 4 * cp2) = *(unsigned*)&h2v;
        }
    }

    // ---- distance weights ws[k][n] (fp32, applied post-MMA) ----
    const float* cb = coords + (size_t)bt * 3 * Ndim;
    for (int idx = tid; idx < Kdim * TILE_N; idx += THREADS) {
        int k = idx >> 7, n = idx & 127;
        int mc = n0 + n, mt2 = mc + k - 4;
        float cx = 0.f, cy = 0.f, cz = 0.f;
        if (mt2 >= 0 && mt2 < Ndim) { cx = cb[mt2]; cy = cb[Ndim + mt2]; cz = cb[2 * Ndim + mt2]; }
        float dx = cx - cb[mc], dy = cy - cb[Ndim + mc], dz = cz - cb[2 * Ndim + mc];
        float d2 = dx * dx + dy * dy + dz * dz;
        ws[k * 128 + n] = fmaxf(1.0f - sqrtf(d2) * inv_sigma, 0.0f);
    }
    asm volatile("cp.async.wait_group 0;" ::: "memory");
    __syncthreads();                             // the ONLY barrier

    // ---- 9 GEMMs (K=32 each); warp tile 32f x 64n ----
    const int fh = warp >> 1;                    // f-half (32 rows)
    const int nh = warp & 1;                     // n-half (64 cols)
    const int g  = lane >> 3, rr = lane & 7;

    // A lane offset within a 16fx16k x4 tile
    const uint32_t aoff = (uint32_t)(((g & 1) * 8 + rr) * PROW + (g >> 1) * 16);
    // B lane offset within a 16nx16k x4 tile
    const uint32_t boff = (uint32_t)(((lane >> 4) * 8 + (lane & 7) + nh * 64) * PROW
                                     + ((lane >> 3) & 1) * 16);

    float acc[2][8][4];
    #pragma unroll
    for (int m = 0; m < 2; m++)
        #pragma unroll
        for (int j = 0; j < 8; j++)
            #pragma unroll
            for (int q = 0; q < 4; q++) acc[m][j][q] = 0.0f;

    const int wcol0 = nh * 64 + (lane & 3) * 2;

    #pragma unroll
    for (int k = 0; k < 9; k++) {
        // A fragments for this k: [m][s], reused across all 4 n-substeps
        const uint32_t ab = smb + OFF_A + (uint32_t)k * (Fdim * PROW)
                          + (uint32_t)(fh * 32) * PROW + aoff;
        uint32_t a[2][2][4];
        #pragma unroll
        for (int m = 0; m < 2; m++)
            #pragma unroll
            for (int s = 0; s < 2; s++)
                LDSM_X4(a[m][s][0], a[m][s][1], a[m][s][2], a[m][s][3],
                        ab + (uint32_t)(m * 16) * PROW + s * 32);

        const uint32_t bk = smb + OFF_XT + (uint32_t)k * PROW + boff;

        #pragma unroll
        for (int h2 = 0; h2 < 4; h2++) {         // 16n per substep
            float tmp[2][2][4];
            #pragma unroll
            for (int m = 0; m < 2; m++)
                #pragma unroll
                for (int nf = 0; nf < 2; nf++)
                    #pragma unroll
                    for (int q = 0; q < 4; q++) tmp[m][nf][q] = 0.0f;

            #pragma unroll
            for (int s = 0; s < 2; s++) {
                uint32_t b[4];
                LDSM_X4(b[0], b[1], b[2], b[3],
                        bk + (uint32_t)(h2 * 16) * PROW + s * 32);
                #pragma unroll
                for (int m = 0; m < 2; m++) {
                    MMAF16(tmp[m][0], a[m][s], b[0], b[1]);
                    MMAF16(tmp[m][1], a[m][s], b[2], b[3]);
                }
            }
            // scale by w[k][n] (exact fp32) and accumulate
            #pragma unroll
            for (int nf = 0; nf < 2; nf++) {
                float2 wv = *(float2*)(ws + k * 128 + wcol0 + h2 * 16 + nf * 8);
                #pragma unroll
                for (int m = 0; m < 2; m++) {
                    acc[m][h2 * 2 + nf][0] += wv.x * tmp[m][nf][0];
                    acc[m][h2 * 2 + nf][1] += wv.y * tmp[m][nf][1];
                    acc[m][h2 * 2 + nf][2] += wv.x * tmp[m][nf][2];
                    acc[m][h2 * 2 + nf][3] += wv.y * tmp[m][nf][3];
                }
            }
        }
    }

    // ---- epilogue: register fragments -> gmem ----
    float* ob = out + (size_t)bt * Fdim * Ndim;
    const int drow = lane >> 2;
    const int dcol = (lane & 3) * 2;
    #pragma unroll
    for (int m = 0; m < 2; m++) {
        #pragma unroll
        for (int j = 0; j < 8; j++) {
            int f  = fh * 32 + m * 16 + drow;
            int nc = n0 + nh * 64 + j * 8 + dcol;
            *(float2*)&ob[(size_t)f * Ndim + nc]       = make_float2(acc[m][j][0], acc[m][j][1]);
            *(float2*)&ob[(size_t)(f + 8) * Ndim + nc] = make_float2(acc[m][j][2], acc[m][j][3]);
        }
    }
}

extern "C" void kernel_launch(void* const* d_in, const int* in_sizes, int n_in,
                              void* d_out, int out_size)
{
    const float*    x      = (const float*)d_in[0];
    const float*    coords = (const float*)d_in[1];
    const float*    w      = (const float*)d_in[2];
    const unsigned* sigma  = (const unsigned*)d_in[3];
    float*          out    = (float*)d_out;

    static int smem_set = 0;
    if (!smem_set) {
        cudaFuncSetAttribute(sepconv_mma_kernel,
                             cudaFuncAttributeMaxDynamicSharedMemorySize, SMEM_TOTAL);
        smem_set = 1;
    }

    prep_w<<<(Tdim * Kdim * Fdim * Cdim + 255) / 256, 256>>>(w);

    dim3 grid(Ndim / TILE_N, Bdim * Tdim);
    sepconv_mma_kernel<<<grid, THREADS, SMEM_TOTAL>>>(x, coords, sigma, out);
}

// round 15
// speedup vs baseline: 3.4444x; 1.0839x over previous
#include <cuda_runtime.h>
#include <cuda_fp16.h>
#include <cstdint>

#define Bdim 4
#define Tdim 4
#define Cdim 32
#define Ndim 16384
#define Fdim 64
#define Kdim 9
#define TILE_N 128
#define THREADS 128

// pitch: 32 fp16 = 64B data + 16B pad = 80B (20-word stride, conflict-free ldmatrix)
#define PROW 80
// smem layout (A no longer staged in smem)
#define OFF_XT 0                        // 136 n-rows x 80B = 10880
#define OFF_WS 10880                    // float [9][128]   =  4608
#define SMEM_TOTAL 15488

// A weights in FRAGMENT ORDER: [t][k][fh][m][s] -> 128 uint32 (lane*4 + reg i)
// element: f = fh*32 + m*16 + (i&1)*8 + (l>>2), c = s*16 + (i>>1)*8 + 2*(l&3) (+1)
__device__ __align__(16) unsigned g_wAf[Tdim * Kdim * 2 * 2 * 2 * 128];   // 147456 B

__global__ void prep_w(const float* __restrict__ w) {
    int idx = blockIdx.x * 256 + threadIdx.x;
    if (idx >= Tdim * Kdim * 2 * 2 * 2 * 128) return;   // 36864
    int i  = idx & 3;
    int l  = (idx >> 2) & 31;
    int s  = (idx >> 7) & 1;
    int m  = (idx >> 8) & 1;
    int fh = (idx >> 9) & 1;
    int r  = idx >> 10;                  // t*9 + k
    int k  = r % 9, t = r / 9;
    int f  = fh * 32 + m * 16 + (i & 1) * 8 + (l >> 2);
    int c  = s * 16 + (i >> 1) * 8 + 2 * (l & 3);
    float v0 = w[((t * Fdim + f) * Cdim + c) * Kdim + k];
    float v1 = w[((t * Fdim + f) * Cdim + c + 1) * Kdim + k];
    __half2 h2v = __floats2half2_rn(v0, v1);
    g_wAf[idx] = *(unsigned*)&h2v;
}

__device__ __forceinline__ uint32_t smem_u32(const void* p) {
    uint32_t a;
    asm("{ .reg .u64 t; cvta.to.shared.u64 t, %1; cvt.u32.u64 %0, t; }" : "=r"(a) : "l"(p));
    return a;
}

#define LDSM_X4(r0,r1,r2,r3, addr) \
    asm volatile("ldmatrix.sync.aligned.m8n8.x4.shared.b16 {%0,%1,%2,%3}, [%4];" \
        : "=r"(r0),"=r"(r1),"=r"(r2),"=r"(r3) : "r"(addr))

#define MMAF16(c, a, b0,b1) \
    asm volatile("mma.sync.aligned.m16n8k16.row.col.f32.f16.f16.f32 " \
        "{%0,%1,%2,%3},{%4,%5,%6,%7},{%8,%9},{%0,%1,%2,%3};" \
        : "+f"((c)[0]),"+f"((c)[1]),"+f"((c)[2]),"+f"((c)[3]) \
        : "r"((a)[0]),"r"((a)[1]),"r"((a)[2]),"r"((a)[3]),"r"(b0),"r"(b1))

__global__ __launch_bounds__(THREADS, 4)
void sepconv_mma_kernel(const float* __restrict__ x,
                        const float* __restrict__ coords,
                        const unsigned* __restrict__ sigma_p,
                        float* __restrict__ out)
{
    extern __shared__ __align__(16) unsigned char sm[];
    float* ws = (float*)(sm + OFF_WS);     // [9][128]

    const int tid  = threadIdx.x;
    const int warp = tid >> 5;             // 0..3
    const int lane = tid & 31;
    const int bt   = blockIdx.y;
    const int t    = bt & (Tdim - 1);
    const int n0   = blockIdx.x * TILE_N;
    const uint32_t smb = smem_u32(sm);

    unsigned sb = *sigma_p;
    float sigma = (sb < 0x01000000u) ? (float)(int)sb : __uint_as_float(sb);
    float inv_sigma = 1.0f / sigma;

    // ---- xT build: x[c][n0+i-4] -> fp16 at xT[i][c], 136 rows ----
    const float* xb = x + (size_t)bt * Cdim * Ndim;
    #pragma unroll
    for (int it = 0; it < 17; it++) {
        int idx = it * THREADS + tid;
        if (idx < 16 * 136) {
            int cp2 = idx / 136;                 // c pair 0..15
            int i   = idx - cp2 * 136;
            int m   = n0 + i - 4;
            float v0 = 0.0f, v1 = 0.0f;
            if (m >= 0 && m < Ndim) {
                v0 = xb[(size_t)(cp2 * 2) * Ndim + m];
                v1 = xb[(size_t)(cp2 * 2 + 1) * Ndim + m];
            }
            __half2 h2v = __floats2half2_rn(v0, v1);
            *(unsigned*)(sm + OFF_XT + i * PROW + 4 * cp2) = *(unsigned*)&h2v;
        }
    }

    // ---- distance weights ws[k][n] (fp32, applied post-MMA) ----
    const float* cb = coords + (size_t)bt * 3 * Ndim;
    for (int idx = tid; idx < Kdim * TILE_N; idx += THREADS) {
        int k = idx >> 7, n = idx & 127;
        int mc = n0 + n, mt2 = mc + k - 4;
        float cx = 0.f, cy = 0.f, cz = 0.f;
        if (mt2 >= 0 && mt2 < Ndim) { cx = cb[mt2]; cy = cb[Ndim + mt2]; cz = cb[2 * Ndim + mt2]; }
        float dx = cx - cb[mc], dy = cy - cb[Ndim + mc], dz = cz - cb[2 * Ndim + mc];
        float d2 = dx * dx + dy * dy + dz * dz;
        ws[k * 128 + n] = fmaxf(1.0f - sqrtf(d2) * inv_sigma, 0.0f);
    }
    __syncthreads();                             // the ONLY barrier

    // ---- 9 GEMMs (K=32 each); warp tile 32f x 64n; A direct from gmem ----
    const int fh = warp >> 1;                    // f-half (32 rows)
    const int nh = warp & 1;                     // n-half (64 cols)

    // A fragment source: [t][k][fh][m][s] blocks of 32 uint4, lane-indexed.
    // block index = ((( (t*9+k)*2 + fh )*2 + m)*2 + s) = 72t + 8k + 4fh + 2m + s
    const uint4* afrag = (const uint4*)g_wAf;
    const int abase0 = 72 * t + 4 * fh;          // k=0, m=0, s=0

    // B lane offset within a 16nx16k x4 tile
    const uint32_t boff = (uint32_t)(((lane >> 4) * 8 + (lane & 7) + nh * 64) * PROW
                                     + ((lane >> 3) & 1) * 16);

    float acc[2][8][4];
    #pragma unroll
    for (int m = 0; m < 2; m++)
        #pragma unroll
        for (int j = 0; j < 8; j++)
            #pragma unroll
            for (int q = 0; q < 4; q++) acc[m][j][q] = 0.0f;

    const int wcol0 = nh * 64 + (lane & 3) * 2;

    #pragma unroll
    for (int k = 0; k < 9; k++) {
        // A fragments for this k: one coalesced LDG.128 per (m,s), L2-resident
        uint4 av[2][2];
        #pragma unroll
        for (int m = 0; m < 2; m++)
            #pragma unroll
            for (int s = 0; s < 2; s++)
                av[m][s] = __ldg(&afrag[(size_t)(abase0 + k * 8 + m * 2 + s) * 32 + lane]);

        const uint32_t bk = smb + OFF_XT + (uint32_t)k * PROW + boff;

        #pragma unroll
        for (int h2 = 0; h2 < 4; h2++) {         // 16n per substep
            float tmp[2][2][4];
            #pragma unroll
            for (int m = 0; m < 2; m++)
                #pragma unroll
                for (int nf = 0; nf < 2; nf++)
                    #pragma unroll
                    for (int q = 0; q < 4; q++) tmp[m][nf][q] = 0.0f;

            #pragma unroll
            for (int s = 0; s < 2; s++) {
                uint32_t b[4];
                LDSM_X4(b[0], b[1], b[2], b[3],
                        bk + (uint32_t)(h2 * 16) * PROW + s * 32);
                #pragma unroll
                for (int m = 0; m < 2; m++) {
                    MMAF16(tmp[m][0], ((uint32_t*)&av[m][s]), b[0], b[1]);
                    MMAF16(tmp[m][1], ((uint32_t*)&av[m][s]), b[2], b[3]);
                }
            }
            // scale by w[k][n] (exact fp32) and accumulate
            #pragma unroll
            for (int nf = 0; nf < 2; nf++) {
                float2 wv = *(float2*)(ws + k * 128 + wcol0 + h2 * 16 + nf * 8);
                #pragma unroll
                for (int m = 0; m < 2; m++) {
                    acc[m][h2 * 2 + nf][0] += wv.x * tmp[m][nf][0];
                    acc[m][h2 * 2 + nf][1] += wv.y * tmp[m][nf][1];
                    acc[m][h2 * 2 + nf][2] += wv.x * tmp[m][nf][2];
                    acc[m][h2 * 2 + nf][3] += wv.y * tmp[m][nf][3];
                }
            }
        }
    }

    // ---- epilogue: register fragments -> gmem ----
    float* ob = out + (size_t)bt * Fdim * Ndim;
    const int drow = lane >> 2;
    const int dcol = (lane & 3) * 2;
    #pragma unroll
    for (int m = 0; m < 2; m++) {
        #pragma unroll
        for (int j = 0; j < 8; j++) {
            int f  = fh * 32 + m * 16 + drow;
            int nc = n0 + nh * 64 + j * 8 + dcol;
            *(float2*)&ob[(size_t)f * Ndim + nc]       = make_float2(acc[m][j][0], acc[m][j][1]);
            *(float2*)&ob[(size_t)(f + 8) * Ndim + nc] = make_float2(acc[m][j][2], acc[m][j][3]);
        }
    }
}

extern "C" void kernel_launch(void* const* d_in, const int* in_sizes, int n_in,
                              void* d_out, int out_size)
{
    const float*    x      = (const float*)d_in[0];
    const float*    coords = (const float*)d_in[1];
    const float*    w      = (const float*)d_in[2];
    const unsigned* sigma  = (const unsigned*)d_in[3];
    float*          out    = (float*)d_out;

    prep_w<<<(Tdim * Kdim * 2 * 2 * 2 * 128 + 255) / 256, 256>>>(w);

    dim3 grid(Ndim / TILE_N, Bdim * Tdim);
    sepconv_mma_kernel<<<grid, THREADS, SMEM_TOTAL>>>(x, coords, sigma, out);
}